// round 13
// baseline (speedup 1.0000x reference)
#include <cuda_runtime.h>
#include <cstdint>

// MaSIF geodesic conv, GB300 sm_103a — bank-conflict elimination round.
// vs round 11 (211us): conv remapped i=tid&3 + bank-skewed desc layout
// (feature stride 1448, kq stride 360, bin skew 4b+4(b>>3)) -> desc LDS.128
// conflict-free (28 -> 4 wf/bp/warp); ND row stride 256 -> 272 (r-groups on
// disjoint bank halves) -> divide reads conflict-free. ND mainloop unchanged.
//
// Th[v][k][t] = E_v[((k+K0_v)&15) - t + 15]; E_v built with 4 exps/vertex.
// ND:   (25 x 128) @ (128 x 256) in smem, FFMA2 accumulators.
// conv: desc @ W_i + b_i (W via L1/L2), max over 16 rotations, relu.

#define NV    128
#define NBINS 80
#define EPSF  1e-5f
#define NDS   272        // ND row stride (≡16 mod 32 banks)

// desc3 layout: addr = i*DI + kq*DK + 4*b + 4*(b>>3)
#define DK    360        // kq stride (≡8 mod 32)
#define DI    1448       // feature stride (≡8 mod 32), >= 4*DK

// smem float offsets (per-CTA total 57472 bytes -> 3 CTAs/SM)
#define OFF_A     0          // 25 x 128   (dead after ND)
#define OFF_E     3200       // 128 x 33   (dead after ND)
#define OFF_DESC  0          // 4 x 1448 = 5792 — ALIASES A/E (written in divide)
#define OFF_ND    7424       // 25 x 272 = 6800
#define OFF_K0    14224      // 128 ints (16B aligned)
#define OFF_MUR   14352      // 5
#define OFF_ISR   14360      // 5
#define SMEM_FLOATS 14368    // 57472 bytes

typedef unsigned long long u64;

__device__ __forceinline__ u64 pk2(float lo, float hi) {
    u64 r;
    asm("mov.b64 %0, {%1, %2};" : "=l"(r) : "f"(lo), "f"(hi));
    return r;
}
__device__ __forceinline__ void fma2(u64& d, u64 a, u64 b) {
    asm("fma.rn.f32x2 %0, %1, %2, %0;" : "+l"(d) : "l"(a), "l"(b));
}
__device__ __forceinline__ float2 upk2(u64 v) {
    float2 f;
    asm("mov.b64 {%0, %1}, %2;" : "=f"(f.x), "=f"(f.y) : "l"(v));
    return f;
}

// One ND tile: NC columns starting at C0; lane covers kt0 = 4q .. 4q+3.
template<int C0, int NC>
__device__ __forceinline__ void nd_block(const float* __restrict__ s_A,
                                         const float* __restrict__ s_E,
                                         const int* __restrict__ s_K0,
                                         float* __restrict__ s_ND,
                                         int q)
{
    const int kt0  = q * 4;
    const int kg   = q >> 2;            // shared by the lane's 4 kt
    const int boff = 15 - 4 * (q & 3);  // base = ((kg+K0)&15) + boff

    u64 acc2[NC][2];
    #pragma unroll
    for (int c = 0; c < NC; c++) { acc2[c][0] = 0ull; acc2[c][1] = 0ull; }

    #pragma unroll 1
    for (int v = 0; v < NV; v += 4) {
        float4 a4[NC];
        #pragma unroll
        for (int c = 0; c < NC; c++)
            a4[c] = *(const float4*)&s_A[(C0 + c) * NV + v];

        int4 k4 = *(const int4*)&s_K0[v];          // warp-uniform broadcast
        int kvals[4] = {k4.x, k4.y, k4.z, k4.w};

        #pragma unroll
        for (int jv = 0; jv < 4; jv++) {
            const float* Ep = s_E + (v + jv) * 33;
            int base = ((kg + kvals[jv]) & 15) + boff;
            u64 tv01 = pk2(Ep[base],     Ep[base - 1]);
            u64 tv23 = pk2(Ep[base - 2], Ep[base - 3]);
            #pragma unroll
            for (int c = 0; c < NC; c++) {
                float a = (jv == 0) ? a4[c].x : (jv == 1) ? a4[c].y
                        : (jv == 2) ? a4[c].z : a4[c].w;
                u64 aa = pk2(a, a);
                fma2(acc2[c][0], aa, tv01);
                fma2(acc2[c][1], aa, tv23);
            }
        }
    }
    #pragma unroll
    for (int c = 0; c < NC; c++) {
        float2 lo = upk2(acc2[c][0]);
        float2 hi = upk2(acc2[c][1]);
        float4 o;
        o.x = lo.x; o.y = lo.y; o.z = hi.x; o.w = hi.y;
        *(float4*)&s_ND[(C0 + c) * NDS + kt0] = o;
    }
}

__global__ __launch_bounds__(256, 3)
void masif_kernel(const float* __restrict__ rho,
                  const float* __restrict__ theta,
                  const float* __restrict__ feat,
                  const float* __restrict__ mask,
                  const float* __restrict__ mu_rho,
                  const float* __restrict__ sigma_rho,
                  const float* __restrict__ mu_theta,
                  const float* __restrict__ sigma_theta,
                  const float* __restrict__ W,
                  const float* __restrict__ bias,
                  float* __restrict__ out)
{
    extern __shared__ float sm[];
    float* s_A    = sm + OFF_A;
    float* s_E    = sm + OFF_E;
    float* s_ND   = sm + OFF_ND;
    float* s_desc = sm + OFF_DESC;   // aliases A/E (safe: written after ND)
    int*   s_K0   = (int*)(sm + OFF_K0);
    float* s_mur  = sm + OFF_MUR;
    float* s_isr  = sm + OFF_ISR;

    const int tid = threadIdx.x;
    const int n   = blockIdx.x;
    const float two_pi = 6.2831855f;           // float32(2*pi)
    const float step   = two_pi / 16.0f;

    // ---- prologue: small tables ----
    if (tid < 5) {
        s_mur[tid] = mu_rho[tid * 16];
        float s = sigma_rho[tid * 16];
        s_isr[tid] = 1.0f / (s * s + EPSF);
    }
    float st0 = sigma_theta[0];
    const float ist = 1.0f / (st0 * st0 + EPSF);
    __syncthreads();

    // ---- A build (threads 0..127) and E build (threads 128..255) ----
    if (tid < 128) {
        int v = tid;
        float rv = rho[n * NV + v];
        float m  = mask[n * NV + v];
        float4 f4 = ((const float4*)feat)[n * NV + v];
        #pragma unroll
        for (int r = 0; r < 5; r++) {
            float d = rv - s_mur[r];
            float e = __expf(-d * d * s_isr[r]) * m;
            s_A[(20 + r) * NV + v] = e;
            s_A[(0 * 5 + r) * NV + v] = e * f4.x;
            s_A[(1 * 5 + r) * NV + v] = e * f4.y;
            s_A[(2 * 5 + r) * NV + v] = e * f4.z;
            s_A[(3 * 5 + r) * NV + v] = e * f4.w;
        }
    } else {
        // E tables: 31 theta-Gaussian values per vertex, 4 exps each
        int v = tid - 128;
        float th = theta[n * NV + v];
        float kf = floorf(th * (16.0f / two_pi));
        int K0 = (int)kf;
        if (K0 > 15) K0 = 15;
        if (K0 < 0)  K0 = 0;
        float u  = th - (float)K0 * step;
        float E0 = __expf(-ist * u * u);
        float q  = __expf(-ist * step * step);
        float q2 = q * q;
        float rr = __expf(-2.0f * ist * u * step);
        float ri = __expf( 2.0f * ist * u * step);
        float* Ep = s_E + v * 33;
        Ep[15] = E0;
        float e = E0, mlt = rr * q;
        #pragma unroll
        for (int j = 1; j <= 15; j++) { e *= mlt; Ep[15 + j] = e; mlt *= q2; }
        e = E0; mlt = ri * q;
        #pragma unroll
        for (int j = 1; j <= 15; j++) { e *= mlt; Ep[15 - j] = e; mlt *= q2; }
        s_K0[v] = K0;
    }
    __syncthreads();

    // ---- ND matmul: (25 x 128) @ (128 x 256) -> s_ND[25][272-stride], FFMA2 ----
    // 8 warps: col-groups (7,6,6,6) x 2 kt-halves; lane owns 4 kt.
    {
        int w  = tid >> 5;
        int q  = ((w & 1) << 5) | (tid & 31);   // 0..63
        int cg = w >> 1;                        // 0..3, warp-uniform
        if (cg == 0)      nd_block<0, 7>(s_A, s_E, s_K0, s_ND, q);
        else if (cg == 1) nd_block<7, 6>(s_A, s_E, s_K0, s_ND, q);
        else if (cg == 2) nd_block<13, 6>(s_A, s_E, s_K0, s_ND, q);
        else              nd_block<19, 6>(s_A, s_E, s_K0, s_ND, q);
    }
    __syncthreads();

    // ---- divide: shared denominators, 1 rcp per (b, k); 320 items / 256 thr ----
    // writes bank-skewed desc3 (aliases dead A/E region)
    for (int idx = tid; idx < 320; idx += 256) {
        int kq = idx / 80;               // 0..3
        int b  = idx - kq * 80;          // 0..79
        int r  = b >> 4, t = b & 15;
        const float* Dp = s_ND + (20 + r) * NDS + t;
        float rc[4];
        #pragma unroll
        for (int kk = 0; kk < 4; kk++)
            rc[kk] = __fdividef(1.0f, Dp[(kq * 4 + kk) * 16] + EPSF);
        int doff = kq * DK + b * 4 + (b >> 3) * 4;
        #pragma unroll
        for (int i = 0; i < 4; i++) {
            const float* Np = s_ND + (i * 5 + r) * NDS + t;
            float4 o;
            o.x = Np[(kq * 4 + 0) * 16] * rc[0];
            o.y = Np[(kq * 4 + 1) * 16] * rc[1];
            o.z = Np[(kq * 4 + 2) * 16] * rc[2];
            o.w = Np[(kq * 4 + 3) * 16] * rc[3];
            *(float4*)&s_desc[i * DI + doff] = o;
        }
    }
    __syncthreads();

    // ---- conv + max over 16 rot + relu: 160 threads, 2 bins/thread ----
    // i = tid&3 so each desc LDS.128 hits 4 bank-disjoint addresses (1 wf).
    if (tid < 160) {
        int i  = tid & 3;
        int j  = tid >> 2;               // 0..39
        int b0 = j * 2;

        float2 bv = *(const float2*)&bias[i * NBINS + b0];
        u64 accA[8], accB[8];
        u64 bA = pk2(bv.x, bv.x), bB = pk2(bv.y, bv.y);
        #pragma unroll
        for (int jj = 0; jj < 8; jj++) { accA[jj] = bA; accB[jj] = bB; }

        const float* wcol  = W + i * NBINS * NBINS + b0;
        const float* dbase = s_desc + i * DI;
        #pragma unroll 4
        for (int bp = 0; bp < NBINS; bp++) {
            float2 wv = *(const float2*)&wcol[bp * NBINS];
            u64 wa = pk2(wv.x, wv.x);
            u64 wb = pk2(wv.y, wv.y);
            int boff = bp * 4 + (bp >> 3) * 4;
            ulonglong2 q0 = *(const ulonglong2*)(dbase + 0 * DK + boff);
            ulonglong2 q1 = *(const ulonglong2*)(dbase + 1 * DK + boff);
            ulonglong2 q2 = *(const ulonglong2*)(dbase + 2 * DK + boff);
            ulonglong2 q3 = *(const ulonglong2*)(dbase + 3 * DK + boff);
            fma2(accA[0], q0.x, wa); fma2(accB[0], q0.x, wb);
            fma2(accA[1], q0.y, wa); fma2(accB[1], q0.y, wb);
            fma2(accA[2], q1.x, wa); fma2(accB[2], q1.x, wb);
            fma2(accA[3], q1.y, wa); fma2(accB[3], q1.y, wb);
            fma2(accA[4], q2.x, wa); fma2(accB[4], q2.x, wb);
            fma2(accA[5], q2.y, wa); fma2(accB[5], q2.y, wb);
            fma2(accA[6], q3.x, wa); fma2(accB[6], q3.x, wb);
            fma2(accA[7], q3.y, wa); fma2(accB[7], q3.y, wb);
        }
        float mA = -3.4e38f, mB = -3.4e38f;
        #pragma unroll
        for (int jj = 0; jj < 8; jj++) {
            float2 pa = upk2(accA[jj]);
            float2 pb = upk2(accB[jj]);
            mA = fmaxf(mA, fmaxf(pa.x, pa.y));
            mB = fmaxf(mB, fmaxf(pb.x, pb.y));
        }
        float2 o;
        o.x = fmaxf(mA, 0.0f);
        o.y = fmaxf(mB, 0.0f);
        *(float2*)&out[(n * 4 + i) * NBINS + b0] = o;
    }
}

extern "C" void kernel_launch(void* const* d_in, const int* in_sizes, int n_in,
                              void* d_out, int out_size)
{
    const float* rho         = (const float*)d_in[0];
    const float* theta       = (const float*)d_in[1];
    const float* feat        = (const float*)d_in[2];
    const float* mask        = (const float*)d_in[3];
    const float* mu_rho      = (const float*)d_in[4];
    const float* sigma_rho   = (const float*)d_in[5];
    const float* mu_theta    = (const float*)d_in[6];
    const float* sigma_theta = (const float*)d_in[7];
    const float* W           = (const float*)d_in[8];
    const float* bias        = (const float*)d_in[9];
    float* out = (float*)d_out;

    const size_t smem_bytes = SMEM_FLOATS * sizeof(float);   // 57472
    cudaFuncSetAttribute(masif_kernel,
                         cudaFuncAttributeMaxDynamicSharedMemorySize,
                         (int)smem_bytes);

    masif_kernel<<<4096, 256, smem_bytes>>>(
        rho, theta, feat, mask, mu_rho, sigma_rho, mu_theta, sigma_theta,
        W, bias, out);
}

// round 14
// speedup vs baseline: 1.2235x; 1.2235x over previous
#include <cuda_runtime.h>
#include <cstdint>

// MaSIF geodesic conv, GB300 sm_103a — round-11 base + ND stride fix.
// Round-11 kernel (211us) verbatim, except ND row stride 256 -> 272
// (≡16 mod 32 banks): divide-phase scalar N/D reads become conflict-free
// (r=0/r=1 lane groups on disjoint bank halves). Conv keeps the broadcast
// desc layout — round 12 proved divergent "conflict-free" loads lose to
// warp-uniform broadcasts.
//
// Th[v][k][t] = E_v[((k+K0_v)&15) - t + 15]; E_v built with 4 exps/vertex.
// ND:   (25 x 128) @ (128 x 256) in smem, FFMA2 accumulators.
// conv: desc @ W_i + b_i (W via L1/L2), max over 16 rotations, relu.

#define NV    128
#define NBINS 80
#define EPSF  1e-5f
#define NDS   272        // ND row stride (≡16 mod 32 banks)

// smem float offsets (per-CTA total 57472 bytes -> 3 CTAs/SM)
#define OFF_A     0          // 25 x 128   (dead after ND)
#define OFF_E     3200       // 128 x 33   (dead after ND)
#define OFF_DESC  0          // 4 x 80 x 20 = 6400 — ALIASES A/E (written in divide)
#define OFF_ND    7424       // 25 x 272 = 6800
#define OFF_K0    14224     // 128 ints (16B aligned)
#define OFF_MUR   14352      // 5
#define OFF_ISR   14360      // 5
#define SMEM_FLOATS 14368    // 57472 bytes

typedef unsigned long long u64;

__device__ __forceinline__ u64 pk2(float lo, float hi) {
    u64 r;
    asm("mov.b64 %0, {%1, %2};" : "=l"(r) : "f"(lo), "f"(hi));
    return r;
}
__device__ __forceinline__ void fma2(u64& d, u64 a, u64 b) {
    asm("fma.rn.f32x2 %0, %1, %2, %0;" : "+l"(d) : "l"(a), "l"(b));
}
__device__ __forceinline__ float2 upk2(u64 v) {
    float2 f;
    asm("mov.b64 {%0, %1}, %2;" : "=f"(f.x), "=f"(f.y) : "l"(v));
    return f;
}

// One ND tile: NC columns starting at C0; lane covers kt0 = 4q .. 4q+3.
template<int C0, int NC>
__device__ __forceinline__ void nd_block(const float* __restrict__ s_A,
                                         const float* __restrict__ s_E,
                                         const int* __restrict__ s_K0,
                                         float* __restrict__ s_ND,
                                         int q)
{
    const int kt0  = q * 4;
    const int kg   = q >> 2;            // shared by the lane's 4 kt
    const int boff = 15 - 4 * (q & 3);  // base = ((kg+K0)&15) + boff

    u64 acc2[NC][2];
    #pragma unroll
    for (int c = 0; c < NC; c++) { acc2[c][0] = 0ull; acc2[c][1] = 0ull; }

    #pragma unroll 1
    for (int v = 0; v < NV; v += 4) {
        float4 a4[NC];
        #pragma unroll
        for (int c = 0; c < NC; c++)
            a4[c] = *(const float4*)&s_A[(C0 + c) * NV + v];

        int4 k4 = *(const int4*)&s_K0[v];          // warp-uniform broadcast
        int kvals[4] = {k4.x, k4.y, k4.z, k4.w};

        #pragma unroll
        for (int jv = 0; jv < 4; jv++) {
            const float* Ep = s_E + (v + jv) * 33;
            int base = ((kg + kvals[jv]) & 15) + boff;
            u64 tv01 = pk2(Ep[base],     Ep[base - 1]);
            u64 tv23 = pk2(Ep[base - 2], Ep[base - 3]);
            #pragma unroll
            for (int c = 0; c < NC; c++) {
                float a = (jv == 0) ? a4[c].x : (jv == 1) ? a4[c].y
                        : (jv == 2) ? a4[c].z : a4[c].w;
                u64 aa = pk2(a, a);
                fma2(acc2[c][0], aa, tv01);
                fma2(acc2[c][1], aa, tv23);
            }
        }
    }
    #pragma unroll
    for (int c = 0; c < NC; c++) {
        float2 lo = upk2(acc2[c][0]);
        float2 hi = upk2(acc2[c][1]);
        float4 o;
        o.x = lo.x; o.y = lo.y; o.z = hi.x; o.w = hi.y;
        *(float4*)&s_ND[(C0 + c) * NDS + kt0] = o;
    }
}

__global__ __launch_bounds__(256, 3)
void masif_kernel(const float* __restrict__ rho,
                  const float* __restrict__ theta,
                  const float* __restrict__ feat,
                  const float* __restrict__ mask,
                  const float* __restrict__ mu_rho,
                  const float* __restrict__ sigma_rho,
                  const float* __restrict__ mu_theta,
                  const float* __restrict__ sigma_theta,
                  const float* __restrict__ W,
                  const float* __restrict__ bias,
                  float* __restrict__ out)
{
    extern __shared__ float sm[];
    float* s_A    = sm + OFF_A;
    float* s_E    = sm + OFF_E;
    float* s_ND   = sm + OFF_ND;
    float* s_desc = sm + OFF_DESC;   // aliases A/E (safe: written after ND)
    int*   s_K0   = (int*)(sm + OFF_K0);
    float* s_mur  = sm + OFF_MUR;
    float* s_isr  = sm + OFF_ISR;

    const int tid = threadIdx.x;
    const int n   = blockIdx.x;
    const float two_pi = 6.2831855f;           // float32(2*pi)
    const float step   = two_pi / 16.0f;

    // ---- prologue: small tables ----
    if (tid < 5) {
        s_mur[tid] = mu_rho[tid * 16];
        float s = sigma_rho[tid * 16];
        s_isr[tid] = 1.0f / (s * s + EPSF);
    }
    float st0 = sigma_theta[0];
    const float ist = 1.0f / (st0 * st0 + EPSF);
    __syncthreads();

    // ---- A build (threads 0..127) and E build (threads 128..255) ----
    if (tid < 128) {
        int v = tid;
        float rv = rho[n * NV + v];
        float m  = mask[n * NV + v];
        float4 f4 = ((const float4*)feat)[n * NV + v];
        #pragma unroll
        for (int r = 0; r < 5; r++) {
            float d = rv - s_mur[r];
            float e = __expf(-d * d * s_isr[r]) * m;
            s_A[(20 + r) * NV + v] = e;
            s_A[(0 * 5 + r) * NV + v] = e * f4.x;
            s_A[(1 * 5 + r) * NV + v] = e * f4.y;
            s_A[(2 * 5 + r) * NV + v] = e * f4.z;
            s_A[(3 * 5 + r) * NV + v] = e * f4.w;
        }
    } else {
        // E tables: 31 theta-Gaussian values per vertex, 4 exps each
        int v = tid - 128;
        float th = theta[n * NV + v];
        float kf = floorf(th * (16.0f / two_pi));
        int K0 = (int)kf;
        if (K0 > 15) K0 = 15;
        if (K0 < 0)  K0 = 0;
        float u  = th - (float)K0 * step;
        float E0 = __expf(-ist * u * u);
        float q  = __expf(-ist * step * step);
        float q2 = q * q;
        float rr = __expf(-2.0f * ist * u * step);
        float ri = __expf( 2.0f * ist * u * step);
        float* Ep = s_E + v * 33;
        Ep[15] = E0;
        float e = E0, mlt = rr * q;
        #pragma unroll
        for (int j = 1; j <= 15; j++) { e *= mlt; Ep[15 + j] = e; mlt *= q2; }
        e = E0; mlt = ri * q;
        #pragma unroll
        for (int j = 1; j <= 15; j++) { e *= mlt; Ep[15 - j] = e; mlt *= q2; }
        s_K0[v] = K0;
    }
    __syncthreads();

    // ---- ND matmul: (25 x 128) @ (128 x 256) -> s_ND (stride 272), FFMA2 ----
    // 8 warps: col-groups (7,6,6,6) x 2 kt-halves; lane owns 4 kt.
    {
        int w  = tid >> 5;
        int q  = ((w & 1) << 5) | (tid & 31);   // 0..63
        int cg = w >> 1;                        // 0..3, warp-uniform
        if (cg == 0)      nd_block<0, 7>(s_A, s_E, s_K0, s_ND, q);
        else if (cg == 1) nd_block<7, 6>(s_A, s_E, s_K0, s_ND, q);
        else if (cg == 2) nd_block<13, 6>(s_A, s_E, s_K0, s_ND, q);
        else              nd_block<19, 6>(s_A, s_E, s_K0, s_ND, q);
    }
    __syncthreads();

    // ---- divide: shared denominators, 1 rcp per (b, k); 320 items / 256 thr ----
    // (writes s_desc, which aliases the now-dead A/E region)
    for (int idx = tid; idx < 320; idx += 256) {
        int kq = idx / 80;               // 0..3
        int b  = idx - kq * 80;          // 0..79
        int r  = b >> 4, t = b & 15;
        const float* Dp = s_ND + (20 + r) * NDS + t;
        float rc[4];
        #pragma unroll
        for (int kk = 0; kk < 4; kk++)
            rc[kk] = __fdividef(1.0f, Dp[(kq * 4 + kk) * 16] + EPSF);
        #pragma unroll
        for (int i = 0; i < 4; i++) {
            const float* Np = s_ND + (i * 5 + r) * NDS + t;
            float4 o;
            o.x = Np[(kq * 4 + 0) * 16] * rc[0];
            o.y = Np[(kq * 4 + 1) * 16] * rc[1];
            o.z = Np[(kq * 4 + 2) * 16] * rc[2];
            o.w = Np[(kq * 4 + 3) * 16] * rc[3];
            *(float4*)&s_desc[(i * NBINS + b) * 20 + kq * 4] = o;
        }
    }
    __syncthreads();

    // ---- conv + max over 16 rot + relu: 160 threads, 2 bins/thread ----
    // W via L2 (coalesced float2); desc LDS.128 broadcasts feed both bins.
    if (tid < 160) {
        int i  = tid / 40;
        int j  = tid - i * 40;
        int b0 = j * 2;

        float2 bv = *(const float2*)&bias[i * NBINS + b0];
        u64 accA[8], accB[8];
        u64 bA = pk2(bv.x, bv.x), bB = pk2(bv.y, bv.y);
        #pragma unroll
        for (int jj = 0; jj < 8; jj++) { accA[jj] = bA; accB[jj] = bB; }

        const float* wcol  = W + i * NBINS * NBINS + b0;
        const float* dbase = s_desc + i * NBINS * 20;
        #pragma unroll 4
        for (int bp = 0; bp < NBINS; bp++) {
            float2 wv = *(const float2*)&wcol[bp * NBINS];
            u64 wa = pk2(wv.x, wv.x);
            u64 wb = pk2(wv.y, wv.y);
            const float* dp = dbase + bp * 20;             // 16B-aligned
            ulonglong2 q0 = *(const ulonglong2*)(dp);        // k0..k3
            ulonglong2 q1 = *(const ulonglong2*)(dp + 4);    // k4..k7
            ulonglong2 q2 = *(const ulonglong2*)(dp + 8);    // k8..k11
            ulonglong2 q3 = *(const ulonglong2*)(dp + 12);   // k12..k15
            fma2(accA[0], q0.x, wa); fma2(accB[0], q0.x, wb);
            fma2(accA[1], q0.y, wa); fma2(accB[1], q0.y, wb);
            fma2(accA[2], q1.x, wa); fma2(accB[2], q1.x, wb);
            fma2(accA[3], q1.y, wa); fma2(accB[3], q1.y, wb);
            fma2(accA[4], q2.x, wa); fma2(accB[4], q2.x, wb);
            fma2(accA[5], q2.y, wa); fma2(accB[5], q2.y, wb);
            fma2(accA[6], q3.x, wa); fma2(accB[6], q3.x, wb);
            fma2(accA[7], q3.y, wa); fma2(accB[7], q3.y, wb);
        }
        float mA = -3.4e38f, mB = -3.4e38f;
        #pragma unroll
        for (int jj = 0; jj < 8; jj++) {
            float2 pa = upk2(accA[jj]);
            float2 pb = upk2(accB[jj]);
            mA = fmaxf(mA, fmaxf(pa.x, pa.y));
            mB = fmaxf(mB, fmaxf(pb.x, pb.y));
        }
        float2 o;
        o.x = fmaxf(mA, 0.0f);
        o.y = fmaxf(mB, 0.0f);
        *(float2*)&out[(n * 4 + i) * NBINS + b0] = o;
    }
}

extern "C" void kernel_launch(void* const* d_in, const int* in_sizes, int n_in,
                              void* d_out, int out_size)
{
    const float* rho         = (const float*)d_in[0];
    const float* theta       = (const float*)d_in[1];
    const float* feat        = (const float*)d_in[2];
    const float* mask        = (const float*)d_in[3];
    const float* mu_rho      = (const float*)d_in[4];
    const float* sigma_rho   = (const float*)d_in[5];
    const float* mu_theta    = (const float*)d_in[6];
    const float* sigma_theta = (const float*)d_in[7];
    const float* W           = (const float*)d_in[8];
    const float* bias        = (const float*)d_in[9];
    float* out = (float*)d_out;

    const size_t smem_bytes = SMEM_FLOATS * sizeof(float);   // 57472
    cudaFuncSetAttribute(masif_kernel,
                         cudaFuncAttributeMaxDynamicSharedMemorySize,
                         (int)smem_bytes);

    masif_kernel<<<4096, 256, smem_bytes>>>(
        rho, theta, feat, mask, mu_rho, sigma_rho, mu_theta, sigma_theta,
        W, bias, out);
}